// round 1
// baseline (speedup 1.0000x reference)
#include <cuda_runtime.h>

// Problem constants
#define Bsz 4096
#define Vn  50
#define Fn  15
#define Hn  256
#define Gn  1024   // 4*H

// ---------------- scratch (static device globals; no allocation) ----------
__device__ float g_h1[Bsz * Hn];
__device__ float g_c1[Bsz * Hn];
__device__ float g_h2[Bsz * Hn];
__device__ float g_c2[Bsz * Hn];
__device__ float g_gates[Bsz * Gn];
__device__ float g_m1[Bsz * 1024];
__device__ float g_m2[Bsz * 1024];
__device__ float g_m3[Bsz * 512];
__device__ float g_m4[Bsz * 256];
__device__ float g_pre2[Bsz * Gn];

__device__ __forceinline__ float sigf(float x) { return 1.0f / (1.0f + expf(-x)); }

// ---------------- zero the recurrent states (every launch; deterministic) --
__global__ void zero_states_kernel() {
    int idx = blockIdx.x * blockDim.x + threadIdx.x;
    if (idx < Bsz * Hn) {
        g_h1[idx] = 0.f; g_c1[idx] = 0.f;
        g_h2[idx] = 0.f; g_c2[idx] = 0.f;
    }
}

// ---------------- fused SGEMM -----------------------------------------------
// C[m,n] = act( sum_k A[m,k]*W[n,k]  (K mult of 8, float4 A loads)
//             + sum_k A2[m,k]*W2[n,k] (small K2 <= 16 tail, scalar loads)
//             + b1[n] + b2[n] + addmat[m,n] )
// Block tile 128x128, 256 threads, 8x8 per-thread microtile, K-tile 8.
template <int ACT>
__global__ void __launch_bounds__(256, 2) gemm_fused(
    const float* __restrict__ A,  int lda,
    const float* __restrict__ W,  int ldw, int K,
    const float* __restrict__ A2, int lda2,
    const float* __restrict__ W2, int ldw2, int K2,
    const float* __restrict__ b1, const float* __restrict__ b2,
    const float* __restrict__ addmat,
    float* __restrict__ C, int N)
{
    __shared__ float As[16][128];
    __shared__ float Bs[16][128];

    const int tid = threadIdx.x;
    const int tx = tid & 15;        // column group (n)
    const int ty = tid >> 4;        // row group (m)
    const int m0 = blockIdx.y * 128;
    const int n0 = blockIdx.x * 128;

    float acc[8][8];
#pragma unroll
    for (int i = 0; i < 8; i++)
#pragma unroll
        for (int j = 0; j < 8; j++) acc[i][j] = 0.f;

    const int lrow = tid >> 1;          // 0..127
    const int lcol = (tid & 1) * 4;     // 0 or 4
    const float* Ag = A + (size_t)(m0 + lrow) * lda + lcol;
    const float* Wg = W + (size_t)(n0 + lrow) * ldw + lcol;

    for (int k0 = 0; k0 < K; k0 += 8) {
        // A tile, float4 (all A buffers have lda % 4 == 0 and are 16B-aligned)
        float4 av = *(const float4*)(Ag + k0);
        As[lcol + 0][lrow] = av.x;
        As[lcol + 1][lrow] = av.y;
        As[lcol + 2][lrow] = av.z;
        As[lcol + 3][lrow] = av.w;
        // W tile, scalar (handles odd ldw like 271 and offset bases)
        const float* wp = Wg + k0;
        Bs[lcol + 0][lrow] = wp[0];
        Bs[lcol + 1][lrow] = wp[1];
        Bs[lcol + 2][lrow] = wp[2];
        Bs[lcol + 3][lrow] = wp[3];
        __syncthreads();

#pragma unroll
        for (int kk = 0; kk < 8; kk++) {
            float4 a0 = *(const float4*)&As[kk][ty * 8];
            float4 a1 = *(const float4*)&As[kk][ty * 8 + 4];
            float4 b0 = *(const float4*)&Bs[kk][tx * 8];
            float4 b1v = *(const float4*)&Bs[kk][tx * 8 + 4];
            float a[8] = {a0.x, a0.y, a0.z, a0.w, a1.x, a1.y, a1.z, a1.w};
            float b[8] = {b0.x, b0.y, b0.z, b0.w, b1v.x, b1v.y, b1v.z, b1v.w};
#pragma unroll
            for (int i = 0; i < 8; i++)
#pragma unroll
                for (int j = 0; j < 8; j++) acc[i][j] += a[i] * b[j];
        }
        __syncthreads();
    }

    // Small-K tail (e.g. x_v @ Wih_x.T with K2 = 15)
    if (K2 > 0) {
        for (int idx = tid; idx < 128 * K2; idx += 256) {
            int m = idx & 127;
            int k = idx >> 7;
            As[k][m] = A2[(size_t)(m0 + m) * lda2 + k];
            Bs[k][m] = W2[(size_t)(n0 + m) * ldw2 + k];
        }
        __syncthreads();
        for (int kk = 0; kk < K2; kk++) {
            float4 a0 = *(const float4*)&As[kk][ty * 8];
            float4 a1 = *(const float4*)&As[kk][ty * 8 + 4];
            float4 b0 = *(const float4*)&Bs[kk][tx * 8];
            float4 b1v = *(const float4*)&Bs[kk][tx * 8 + 4];
            float a[8] = {a0.x, a0.y, a0.z, a0.w, a1.x, a1.y, a1.z, a1.w};
            float b[8] = {b0.x, b0.y, b0.z, b0.w, b1v.x, b1v.y, b1v.z, b1v.w};
#pragma unroll
            for (int i = 0; i < 8; i++)
#pragma unroll
                for (int j = 0; j < 8; j++) acc[i][j] += a[i] * b[j];
        }
    }

    // Epilogue
    float bn[8];
#pragma unroll
    for (int j = 0; j < 8; j++) {
        int n = n0 + tx * 8 + j;
        float t = 0.f;
        if (b1) t += b1[n];
        if (b2) t += b2[n];
        bn[j] = t;
    }
#pragma unroll
    for (int i = 0; i < 8; i++) {
        int m = m0 + ty * 8 + i;
        float* crow = C + (size_t)m * N + n0 + tx * 8;
        const float* ar = addmat ? (addmat + (size_t)m * N + n0 + tx * 8) : nullptr;
#pragma unroll
        for (int j = 0; j < 8; j++) {
            float v = acc[i][j] + bn[j];
            if (ar) v += ar[j];
            if (ACT == 1) v = fmaxf(v, 0.f);
            crow[j] = v;
        }
    }
}

// ---------------- LSTM elementwise update (cell 1) --------------------------
__global__ void lstm_update_kernel(const float* __restrict__ gates,
                                   float* __restrict__ h, float* __restrict__ c) {
    int idx = blockIdx.x * blockDim.x + threadIdx.x;
    if (idx >= Bsz * Hn) return;
    int b = idx >> 8;         // / Hn
    int j = idx & 255;        // % Hn
    const float* gr = gates + (size_t)b * Gn;
    float ig = sigf(gr[j]);
    float fg = sigf(gr[Hn + j]);
    float gg = tanhf(gr[2 * Hn + j]);
    float og = sigf(gr[3 * Hn + j]);
    float cn = fg * c[idx] + ig * gg;
    c[idx] = cn;
    h[idx] = og * tanhf(cn);
}

// ---------------- LSTM2 update + pi head (one block per batch row) ----------
__global__ void lstm2_update_pi_kernel(const float* __restrict__ gates,
                                       float* __restrict__ h, float* __restrict__ c,
                                       const float* __restrict__ piW,
                                       const float* __restrict__ pib,
                                       float* __restrict__ out, int v) {
    int b = blockIdx.x;
    int j = threadIdx.x;   // 0..255
    const float* gr = gates + (size_t)b * Gn;
    float ig = sigf(gr[j]);
    float fg = sigf(gr[Hn + j]);
    float gg = tanhf(gr[2 * Hn + j]);
    float og = sigf(gr[3 * Hn + j]);
    size_t idx = (size_t)b * Hn + j;
    float cn = fg * c[idx] + ig * gg;
    c[idx] = cn;
    float hn = og * tanhf(cn);
    h[idx] = hn;

    // dot(hn_row, piW) via warp + smem reduction
    float p = hn * piW[j];
#pragma unroll
    for (int off = 16; off > 0; off >>= 1)
        p += __shfl_down_sync(0xffffffffu, p, off);
    __shared__ float red[8];
    if ((j & 31) == 0) red[j >> 5] = p;
    __syncthreads();
    if (j == 0) {
        float s = 0.f;
#pragma unroll
        for (int w = 0; w < 8; w++) s += red[w];
        out[(size_t)b * Vn + v] = tanhf(s + pib[0]);
    }
}

// ---------------- launch ----------------------------------------------------
extern "C" void kernel_launch(void* const* d_in, const int* in_sizes, int n_in,
                              void* d_out, int out_size) {
    const float* state     = (const float*)d_in[0];   // [4096, 750]
    const float* l1_Wih    = (const float*)d_in[1];   // [1024, 15]
    const float* l1_Whh    = (const float*)d_in[2];   // [1024, 256]
    const float* l1_bih    = (const float*)d_in[3];   // [1024]
    const float* l1_bhh    = (const float*)d_in[4];   // [1024]
    const float* fc1_W     = (const float*)d_in[5];   // [1024, 256]
    const float* fc1_b     = (const float*)d_in[6];
    const float* fc2_W     = (const float*)d_in[7];   // [1024, 1024]
    const float* fc2_b     = (const float*)d_in[8];
    const float* fc3_W     = (const float*)d_in[9];   // [512, 1024]
    const float* fc3_b     = (const float*)d_in[10];
    const float* fc4_W     = (const float*)d_in[11];  // [256, 512]
    const float* fc4_b     = (const float*)d_in[12];
    const float* l2_Wih    = (const float*)d_in[13];  // [1024, 271]  (x:0..14, mlp:15..270)
    const float* l2_Whh    = (const float*)d_in[14];  // [1024, 256]
    const float* l2_bih    = (const float*)d_in[15];
    const float* l2_bhh    = (const float*)d_in[16];
    const float* pi_W      = (const float*)d_in[17];  // [1, 256]
    const float* pi_b      = (const float*)d_in[18];  // [1]
    float* out = (float*)d_out;                        // [4096, 50]

    float* h1 = nullptr; float* c1 = nullptr;
    float* h2 = nullptr; float* c2 = nullptr;
    float* gates = nullptr; float* m1 = nullptr; float* m2 = nullptr;
    float* m3 = nullptr; float* m4 = nullptr; float* pre2 = nullptr;
    cudaGetSymbolAddress((void**)&h1, g_h1);
    cudaGetSymbolAddress((void**)&c1, g_c1);
    cudaGetSymbolAddress((void**)&h2, g_h2);
    cudaGetSymbolAddress((void**)&c2, g_c2);
    cudaGetSymbolAddress((void**)&gates, g_gates);
    cudaGetSymbolAddress((void**)&m1, g_m1);
    cudaGetSymbolAddress((void**)&m2, g_m2);
    cudaGetSymbolAddress((void**)&m3, g_m3);
    cudaGetSymbolAddress((void**)&m4, g_m4);
    cudaGetSymbolAddress((void**)&pre2, g_pre2);

    zero_states_kernel<<<(Bsz * Hn + 255) / 256, 256>>>();

    dim3 ggrid(Gn / 128, Bsz / 128);   // 8 x 32

    // ---- LSTM1 scan: gates = h1@Whh.T + x_v@Wih.T + bih + bhh ----
    for (int v = 0; v < Vn; v++) {
        gemm_fused<0><<<ggrid, 256>>>(
            h1, Hn, l1_Whh, Hn, Hn,
            state + v * Fn, Vn * Fn, l1_Wih, Fn, Fn,
            l1_bih, l1_bhh, nullptr,
            gates, Gn);
        lstm_update_kernel<<<(Bsz * Hn + 255) / 256, 256>>>(gates, h1, c1);
    }

    // ---- MLP stack (relu) ----
    gemm_fused<1><<<dim3(1024 / 128, Bsz / 128), 256>>>(
        h1, Hn, fc1_W, Hn, Hn,
        nullptr, 0, nullptr, 0, 0,
        fc1_b, nullptr, nullptr, m1, 1024);
    gemm_fused<1><<<dim3(1024 / 128, Bsz / 128), 256>>>(
        m1, 1024, fc2_W, 1024, 1024,
        nullptr, 0, nullptr, 0, 0,
        fc2_b, nullptr, nullptr, m2, 1024);
    gemm_fused<1><<<dim3(512 / 128, Bsz / 128), 256>>>(
        m2, 1024, fc3_W, 1024, 1024,
        nullptr, 0, nullptr, 0, 0,
        fc3_b, nullptr, nullptr, m3, 512);
    gemm_fused<1><<<dim3(256 / 128, Bsz / 128), 256>>>(
        m3, 512, fc4_W, 512, 512,
        nullptr, 0, nullptr, 0, 0,
        fc4_b, nullptr, nullptr, m4, 256);

    // ---- Step-invariant LSTM2 input precompute:
    //      pre2 = m4 @ Wih[:,15:].T + bih + bhh   (ldw = 271, base offset 15)
    gemm_fused<0><<<dim3(Gn / 128, Bsz / 128), 256>>>(
        m4, 256, l2_Wih + 15, 271, 256,
        nullptr, 0, nullptr, 0, 0,
        l2_bih, l2_bhh, nullptr, pre2, Gn);

    // ---- LSTM2 scan + pi head ----
    for (int v = 0; v < Vn; v++) {
        gemm_fused<0><<<ggrid, 256>>>(
            h2, Hn, l2_Whh, Hn, Hn,
            state + v * Fn, Vn * Fn, l2_Wih, 271, Fn,
            nullptr, nullptr, pre2,
            gates, Gn);
        lstm2_update_pi_kernel<<<Bsz, 256>>>(gates, h2, c2, pi_W, pi_b, out, v);
    }
}

// round 4
// speedup vs baseline: 1.4651x; 1.4651x over previous
#include <cuda_runtime.h>

// Problem constants
#define Bsz 4096
#define Vn  50
#define Fn  15
#define Hn  256
#define Gn  1024   // 4*H

// ---------------- scratch (static device globals; no allocation) ----------
// Ping-pong hidden-state buffers: the fused LSTM epilogue writes h while other
// CTAs still read h as the GEMM A operand -> must write to a distinct buffer.
__device__ float g_h1a[Bsz * Hn];
__device__ float g_h1b[Bsz * Hn];
__device__ float g_c1 [Bsz * Hn];
__device__ float g_h2a[Bsz * Hn];
__device__ float g_h2b[Bsz * Hn];
__device__ float g_c2 [Bsz * Hn];
__device__ float g_m1[Bsz * 1024];
__device__ float g_m2[Bsz * 1024];
__device__ float g_m3[Bsz * 512];
__device__ float g_m4[Bsz * 256];
__device__ float g_pre2[Bsz * Gn];

typedef unsigned long long ull;

__device__ __forceinline__ void dup2(ull& d, float s) {
    asm("mov.b64 %0,{%1,%1};" : "=l"(d) : "f"(s));
}
__device__ __forceinline__ void ffma2(ull& d, ull a, ull b) {
    asm("fma.rn.f32x2 %0,%1,%2,%0;" : "+l"(d) : "l"(a), "l"(b));
}
__device__ __forceinline__ float2 u2f(ull u) {
    float2 f; asm("mov.b64 {%0,%1},%2;" : "=f"(f.x), "=f"(f.y) : "l"(u)); return f;
}
__device__ __forceinline__ float fsig(float x)  { return 1.0f / (1.0f + expf(-x)); }

// ---------------- zero the recurrent states --------------------------------
__global__ void zero_states_kernel() {
    int idx = blockIdx.x * blockDim.x + threadIdx.x;
    if (idx < Bsz * Hn) {
        g_h1a[idx] = 0.f; g_c1[idx] = 0.f;
        g_h2a[idx] = 0.f; g_c2[idx] = 0.f;
    }
}

// ---------------- fused SGEMM (f32x2, double-buffered, fused epilogue) ------
// Block tile 128x128, 256 threads, 8x8 microtile (as 8x4 f32x2 pairs), K-tile 8.
// REMAP: weight row = ((n&3)<<8)|(n>>2) — interleaves the 4 LSTM gates so each
//        thread's 8 output columns = {i,f,g,o} x 2 hidden units.
// EPI: 0 = bias store, 1 = relu store, 2 = LSTM cell update (C <- h_out, cSt <- c)
// W4:  W rows are 16B-aligned with ldw%4==0 -> float4 loads
template <int EPI, int REMAP, int W4>
__global__ void __launch_bounds__(256, 2) gemm2(
    const float* __restrict__ A,  int lda,
    const float* __restrict__ W,  int ldw, int K,
    const float* __restrict__ A2, int lda2,
    const float* __restrict__ W2, int ldw2, int K2,
    const float* __restrict__ b1, const float* __restrict__ b2,
    const float* __restrict__ addmat,
    float* __restrict__ C, int N,
    float* __restrict__ cSt)
{
    __shared__ float As[2][8][128];
    __shared__ float Bs[2][8][128];

    const int tid = threadIdx.x;
    const int tx = tid & 15;        // n-group
    const int ty = tid >> 4;        // m-group
    const int m0 = blockIdx.y * 128;
    const int n0 = blockIdx.x * 128;

    const int lr = tid >> 1;        // 0..127
    const int lc = (tid & 1) * 4;   // 0 or 4
    const int gn = n0 + lr;
    const int wrow = REMAP ? (((gn & 3) << 8) | (gn >> 2)) : gn;
    const float* Ap = A + (size_t)(m0 + lr) * lda + lc;
    const float* Wp = W + (size_t)wrow * ldw + lc;

    ull acc[8][4];
#pragma unroll
    for (int i = 0; i < 8; i++)
#pragma unroll
        for (int j = 0; j < 4; j++) acc[i][j] = 0ull;

    // preload stage 0
    {
        float4 av = *(const float4*)Ap;
        float4 wv;
        if (W4) wv = *(const float4*)Wp;
        else    wv = make_float4(Wp[0], Wp[1], Wp[2], Wp[3]);
        As[0][lc + 0][lr] = av.x; As[0][lc + 1][lr] = av.y;
        As[0][lc + 2][lr] = av.z; As[0][lc + 3][lr] = av.w;
        Bs[0][lc + 0][lr] = wv.x; Bs[0][lc + 1][lr] = wv.y;
        Bs[0][lc + 2][lr] = wv.z; Bs[0][lc + 3][lr] = wv.w;
    }
    __syncthreads();

    int cur = 0;
    for (int k0 = 0; k0 < K; k0 += 8) {
        const bool more = (k0 + 8) < K;
        float4 av2, wv2;
        if (more) {
            av2 = *(const float4*)(Ap + k0 + 8);
            const float* wq = Wp + k0 + 8;
            if (W4) wv2 = *(const float4*)wq;
            else    wv2 = make_float4(wq[0], wq[1], wq[2], wq[3]);
        }
#pragma unroll
        for (int kk = 0; kk < 8; kk++) {
            float4 a0 = *(const float4*)&As[cur][kk][ty * 8];
            float4 a1 = *(const float4*)&As[cur][kk][ty * 8 + 4];
            const ulonglong2* bp = (const ulonglong2*)&Bs[cur][kk][tx * 8];
            ulonglong2 bq0 = bp[0], bq1 = bp[1];
            float ar[8] = {a0.x, a0.y, a0.z, a0.w, a1.x, a1.y, a1.z, a1.w};
#pragma unroll
            for (int i = 0; i < 8; i++) {
                ull aa; dup2(aa, ar[i]);
                ffma2(acc[i][0], aa, bq0.x);
                ffma2(acc[i][1], aa, bq0.y);
                ffma2(acc[i][2], aa, bq1.x);
                ffma2(acc[i][3], aa, bq1.y);
            }
        }
        if (more) {
            int nx = cur ^ 1;
            As[nx][lc + 0][lr] = av2.x; As[nx][lc + 1][lr] = av2.y;
            As[nx][lc + 2][lr] = av2.z; As[nx][lc + 3][lr] = av2.w;
            Bs[nx][lc + 0][lr] = wv2.x; Bs[nx][lc + 1][lr] = wv2.y;
            Bs[nx][lc + 2][lr] = wv2.z; Bs[nx][lc + 3][lr] = wv2.w;
        }
        __syncthreads();
        cur ^= 1;
    }

    // ---- small-K tail (x_v @ Wih_x.T, K2 <= 15) ----
    if (K2 > 0) {
        float (*Ta)[128] = (float(*)[128]) & As[0][0][0];   // 16 rows available
        float (*Tb)[128] = (float(*)[128]) & Bs[0][0][0];
        for (int idx = tid; idx < 128 * K2; idx += 256) {
            int m = idx & 127;
            int k = idx >> 7;
            Ta[k][m] = A2[(size_t)(m0 + m) * lda2 + k];
            int g2 = n0 + m;
            int wr2 = REMAP ? (((g2 & 3) << 8) | (g2 >> 2)) : g2;
            Tb[k][m] = W2[(size_t)wr2 * ldw2 + k];
        }
        __syncthreads();
        for (int kk = 0; kk < K2; kk++) {
            float4 a0 = *(const float4*)&Ta[kk][ty * 8];
            float4 a1 = *(const float4*)&Ta[kk][ty * 8 + 4];
            const ulonglong2* bp = (const ulonglong2*)&Tb[kk][tx * 8];
            ulonglong2 bq0 = bp[0], bq1 = bp[1];
            float ar[8] = {a0.x, a0.y, a0.z, a0.w, a1.x, a1.y, a1.z, a1.w};
#pragma unroll
            for (int i = 0; i < 8; i++) {
                ull aa; dup2(aa, ar[i]);
                ffma2(acc[i][0], aa, bq0.x);
                ffma2(acc[i][1], aa, bq0.y);
                ffma2(acc[i][2], aa, bq1.x);
                ffma2(acc[i][3], aa, bq1.y);
            }
        }
    }

    // ---- epilogue ----
    float add[8];
    if (EPI != 2 || addmat == nullptr) {
#pragma unroll
        for (int j = 0; j < 8; j++) {
            int n = n0 + tx * 8 + j;
            int rn = REMAP ? (((n & 3) << 8) | (n >> 2)) : n;
            float t = 0.f;
            if (b1) t += b1[rn];
            if (b2) t += b2[rn];
            add[j] = t;
        }
    }

    if (EPI == 2) {
        // LSTM cell update: columns are (gate = j&3, hpair p = j>>2)
        const int hbase = (n0 >> 2) + tx * 2;
#pragma unroll
        for (int i = 0; i < 8; i++) {
            int m = m0 + ty * 8 + i;
            float g[8];
#pragma unroll
            for (int j4 = 0; j4 < 4; j4++) {
                float2 f = u2f(acc[i][j4]);
                g[2 * j4] = f.x; g[2 * j4 + 1] = f.y;
            }
            if (addmat) {
                const float4* pr = (const float4*)(addmat + (size_t)m * Gn + n0 + tx * 8);
                float4 p0 = pr[0], p1 = pr[1];
                g[0] += p0.x; g[1] += p0.y; g[2] += p0.z; g[3] += p0.w;
                g[4] += p1.x; g[5] += p1.y; g[6] += p1.z; g[7] += p1.w;
            } else {
#pragma unroll
                for (int j = 0; j < 8; j++) g[j] += add[j];
            }
            size_t ci = (size_t)m * Hn + hbase;
            float2 cold = *(const float2*)(cSt + ci);
            float hv[2], cv[2];
#pragma unroll
            for (int p = 0; p < 2; p++) {
                float iv = fsig(g[4 * p + 0]);
                float fv = fsig(g[4 * p + 1]);
                float gv = tanhf(g[4 * p + 2]);
                float ov = fsig(g[4 * p + 3]);
                float co = (p == 0) ? cold.x : cold.y;
                float cn = fv * co + iv * gv;
                cv[p] = cn;
                hv[p] = ov * tanhf(cn);
            }
            *(float2*)(cSt + ci) = make_float2(cv[0], cv[1]);
            *(float2*)(C + ci)   = make_float2(hv[0], hv[1]);
        }
    } else {
#pragma unroll
        for (int i = 0; i < 8; i++) {
            int m = m0 + ty * 8 + i;
            float o[8];
#pragma unroll
            for (int j4 = 0; j4 < 4; j4++) {
                float2 f = u2f(acc[i][j4]);
                o[2 * j4]     = f.x + add[2 * j4];
                o[2 * j4 + 1] = f.y + add[2 * j4 + 1];
            }
            if (EPI == 1) {
#pragma unroll
                for (int j = 0; j < 8; j++) o[j] = fmaxf(o[j], 0.f);
            }
            float4* cp = (float4*)(C + (size_t)m * N + n0 + tx * 8);
            cp[0] = make_float4(o[0], o[1], o[2], o[3]);
            cp[1] = make_float4(o[4], o[5], o[6], o[7]);
        }
    }
}

// ---------------- pi head: out[b][v] = tanh(h2[b]·piW + pib) ----------------
__global__ void pi_kernel(const float* __restrict__ h2,
                          const float* __restrict__ piW,
                          const float* __restrict__ pib,
                          float* __restrict__ out, int v) {
    int gw = (blockIdx.x * blockDim.x + threadIdx.x) >> 5;
    int lane = threadIdx.x & 31;
    if (gw >= Bsz) return;
    const float* hr = h2 + (size_t)gw * Hn;
    float s = 0.f;
#pragma unroll
    for (int k = lane; k < Hn; k += 32) s += hr[k] * piW[k];
#pragma unroll
    for (int off = 16; off > 0; off >>= 1)
        s += __shfl_down_sync(0xffffffffu, s, off);
    if (lane == 0)
        out[(size_t)gw * Vn + v] = tanhf(s + pib[0]);
}

// ---------------- launch ----------------------------------------------------
extern "C" void kernel_launch(void* const* d_in, const int* in_sizes, int n_in,
                              void* d_out, int out_size) {
    const float* state  = (const float*)d_in[0];   // [4096, 750]
    const float* l1_Wih = (const float*)d_in[1];   // [1024, 15]
    const float* l1_Whh = (const float*)d_in[2];   // [1024, 256]
    const float* l1_bih = (const float*)d_in[3];
    const float* l1_bhh = (const float*)d_in[4];
    const float* fc1_W  = (const float*)d_in[5];   // [1024, 256]
    const float* fc1_b  = (const float*)d_in[6];
    const float* fc2_W  = (const float*)d_in[7];   // [1024, 1024]
    const float* fc2_b  = (const float*)d_in[8];
    const float* fc3_W  = (const float*)d_in[9];   // [512, 1024]
    const float* fc3_b  = (const float*)d_in[10];
    const float* fc4_W  = (const float*)d_in[11];  // [256, 512]
    const float* fc4_b  = (const float*)d_in[12];
    const float* l2_Wih = (const float*)d_in[13];  // [1024, 271]
    const float* l2_Whh = (const float*)d_in[14];  // [1024, 256]
    const float* l2_bih = (const float*)d_in[15];
    const float* l2_bhh = (const float*)d_in[16];
    const float* pi_W   = (const float*)d_in[17];  // [1, 256]
    const float* pi_b   = (const float*)d_in[18];  // [1]
    float* out = (float*)d_out;                    // [4096, 50]

    float *h1a, *h1b, *c1, *h2a, *h2b, *c2, *m1, *m2, *m3, *m4, *pre2;
    cudaGetSymbolAddress((void**)&h1a, g_h1a);
    cudaGetSymbolAddress((void**)&h1b, g_h1b);
    cudaGetSymbolAddress((void**)&c1,  g_c1);
    cudaGetSymbolAddress((void**)&h2a, g_h2a);
    cudaGetSymbolAddress((void**)&h2b, g_h2b);
    cudaGetSymbolAddress((void**)&c2,  g_c2);
    cudaGetSymbolAddress((void**)&m1, g_m1);
    cudaGetSymbolAddress((void**)&m2, g_m2);
    cudaGetSymbolAddress((void**)&m3, g_m3);
    cudaGetSymbolAddress((void**)&m4, g_m4);
    cudaGetSymbolAddress((void**)&pre2, g_pre2);

    zero_states_kernel<<<(Bsz * Hn + 255) / 256, 256>>>();

    dim3 sgrid(Gn / 128, Bsz / 128);   // 8 x 32

    // ---- LSTM1 scan (fused gate GEMM + cell update), ping-pong h ----
    for (int v = 0; v < Vn; v++) {
        const float* hin = (v & 1) ? h1b : h1a;
        float*       hout = (v & 1) ? h1a : h1b;
        gemm2<2, 1, 1><<<sgrid, 256>>>(
            hin, Hn, l1_Whh, Hn, Hn,
            state + v * Fn, Vn * Fn, l1_Wih, Fn, Fn,
            l1_bih, l1_bhh, nullptr,
            hout, Gn, c1);
    }
    // Vn=50 (even): final h1 is in h1a after step v=49 writes h1a
    const float* h1fin = (Vn & 1) ? h1b : h1a;

    // ---- MLP stack (relu) ----
    gemm2<1, 0, 1><<<dim3(1024 / 128, 32), 256>>>(
        h1fin, Hn, fc1_W, Hn, Hn,
        nullptr, 0, nullptr, 0, 0,
        fc1_b, nullptr, nullptr, m1, 1024, nullptr);
    gemm2<1, 0, 1><<<dim3(1024 / 128, 32), 256>>>(
        m1, 1024, fc2_W, 1024, 1024,
        nullptr, 0, nullptr, 0, 0,
        fc2_b, nullptr, nullptr, m2, 1024, nullptr);
    gemm2<1, 0, 1><<<dim3(512 / 128, 32), 256>>>(
        m2, 1024, fc3_W, 1024, 1024,
        nullptr, 0, nullptr, 0, 0,
        fc3_b, nullptr, nullptr, m3, 512, nullptr);
    gemm2<1, 0, 1><<<dim3(256 / 128, 32), 256>>>(
        m3, 512, fc4_W, 512, 512,
        nullptr, 0, nullptr, 0, 0,
        fc4_b, nullptr, nullptr, m4, 256, nullptr);

    // ---- pre2 = m4 @ Wih2[:,15:].T + bih + bhh  (REMAPPED column layout) ----
    gemm2<0, 1, 0><<<sgrid, 256>>>(
        m4, 256, l2_Wih + 15, 271, 256,
        nullptr, 0, nullptr, 0, 0,
        l2_bih, l2_bhh, nullptr, pre2, Gn, nullptr);

    // ---- LSTM2 scan (fused) + pi head, ping-pong h ----
    for (int v = 0; v < Vn; v++) {
        const float* hin = (v & 1) ? h2b : h2a;
        float*       hout = (v & 1) ? h2a : h2b;
        gemm2<2, 1, 1><<<sgrid, 256>>>(
            hin, Hn, l2_Whh, Hn, Hn,
            state + v * Fn, Vn * Fn, l2_Wih, 271, Fn,
            nullptr, nullptr, pre2,
            hout, Gn, c2);
        pi_kernel<<<Bsz / 8, 256>>>(hout, pi_W, pi_b, out, v);
    }
}

// round 5
// speedup vs baseline: 1.7193x; 1.1735x over previous
#include <cuda_runtime.h>

// Problem constants
#define Bsz 4096
#define Vn  50
#define Fn  15
#define Hn  256
#define Gn  1024   // 4*H

// ---------------- scratch (static device globals; no allocation) ----------
__device__ float g_h1a[Bsz * Hn];
__device__ float g_h1b[Bsz * Hn];
__device__ float g_c1 [Bsz * Hn];
__device__ float g_h2a[Bsz * Hn];
__device__ float g_h2b[Bsz * Hn];
__device__ float g_c2 [Bsz * Hn];
__device__ float g_m1[Bsz * 1024];
__device__ float g_m2[Bsz * 1024];
__device__ float g_m3[Bsz * 512];
__device__ float g_m4[Bsz * 256];
__device__ float g_pre2[Bsz * Gn];

typedef unsigned long long ull;

__device__ __forceinline__ void dup2(ull& d, float s) {
    asm("mov.b64 %0,{%1,%1};" : "=l"(d) : "f"(s));
}
__device__ __forceinline__ void ffma2(ull& d, ull a, ull b) {
    asm("fma.rn.f32x2 %0,%1,%2,%0;" : "+l"(d) : "l"(a), "l"(b));
}
__device__ __forceinline__ float2 u2f(ull u) {
    float2 f; asm("mov.b64 {%0,%1},%2;" : "=f"(f.x), "=f"(f.y) : "l"(u)); return f;
}
__device__ __forceinline__ float fsig(float x)  { return 1.0f / (1.0f + expf(-x)); }

// ---------------- zero the recurrent states --------------------------------
__global__ void zero_states_kernel() {
    int idx = blockIdx.x * blockDim.x + threadIdx.x;
    if (idx < Bsz * Hn) {
        g_h1a[idx] = 0.f; g_c1[idx] = 0.f;
        g_h2a[idx] = 0.f; g_c2[idx] = 0.f;
    }
}

// ---------------- fused SGEMM (f32x2, quadrant microtile, K-tile 16) --------
// Block tile 128x128, 256 threads. Thread (tx,ty) owns
//   cols {n0+4tx..+3} U {n0+64+4tx..+3},  rows {m0+4ty..+3} U {m0+64+4ty..+3}
// -> conflict-free LDS.128 for B (4tx word offsets), broadcast A.
// REMAP: weight row = ((n&3)<<8)|(n>>2): each 4-col quadrant = one hidden
//        unit's {i,f,g,o}.
// EPI: 0 = bias store, 1 = relu store, 2 = LSTM cell update
// W4:  ldw%4==0 and 16B-aligned -> float4 W loads
template <int EPI, int REMAP, int W4>
__global__ void __launch_bounds__(256, 2) gemm3(
    const float* __restrict__ A,  int lda,
    const float* __restrict__ W,  int ldw, int K,
    const float* __restrict__ A2, int lda2,
    const float* __restrict__ W2, int ldw2, int K2,
    const float* __restrict__ b1, const float* __restrict__ b2,
    const float* __restrict__ addmat,
    float* __restrict__ C, int N,
    float* __restrict__ cSt)
{
    __shared__ float As[2][16][128];
    __shared__ float Bs[2][16][128];

    const int tid = threadIdx.x;
    const int tx = tid & 15;
    const int ty = tid >> 4;
    const int m0 = blockIdx.y * 128;
    const int n0 = blockIdx.x * 128;

    const int lr = tid >> 1;        // 0..127
    const int lc = (tid & 1) * 8;   // 0 or 8
    const int gn = n0 + lr;
    const int wrow = REMAP ? (((gn & 3) << 8) | (gn >> 2)) : gn;
    const float* Ap = A + (size_t)(m0 + lr) * lda + lc;
    const float* Wp = W + (size_t)wrow * ldw + lc;

    ull acc[8][4];
#pragma unroll
    for (int i = 0; i < 8; i++)
#pragma unroll
        for (int j = 0; j < 4; j++) acc[i][j] = 0ull;

    // ---- preload stage 0 (each thread: 8 A floats + 8 W floats) ----
    {
        float4 a0 = *(const float4*)Ap;
        float4 a1 = *(const float4*)(Ap + 4);
        float4 w0, w1;
        if (W4) { w0 = *(const float4*)Wp; w1 = *(const float4*)(Wp + 4); }
        else {
            w0 = make_float4(Wp[0], Wp[1], Wp[2], Wp[3]);
            w1 = make_float4(Wp[4], Wp[5], Wp[6], Wp[7]);
        }
        As[0][lc + 0][lr] = a0.x; As[0][lc + 1][lr] = a0.y;
        As[0][lc + 2][lr] = a0.z; As[0][lc + 3][lr] = a0.w;
        As[0][lc + 4][lr] = a1.x; As[0][lc + 5][lr] = a1.y;
        As[0][lc + 6][lr] = a1.z; As[0][lc + 7][lr] = a1.w;
        Bs[0][lc + 0][lr] = w0.x; Bs[0][lc + 1][lr] = w0.y;
        Bs[0][lc + 2][lr] = w0.z; Bs[0][lc + 3][lr] = w0.w;
        Bs[0][lc + 4][lr] = w1.x; Bs[0][lc + 5][lr] = w1.y;
        Bs[0][lc + 6][lr] = w1.z; Bs[0][lc + 7][lr] = w1.w;
    }
    __syncthreads();

    int cur = 0;
    for (int k0 = 0; k0 < K; k0 += 16) {
        const bool more = (k0 + 16) < K;
        float4 pa0, pa1, pw0, pw1;
        if (more) {
            pa0 = *(const float4*)(Ap + k0 + 16);
            pa1 = *(const float4*)(Ap + k0 + 20);
            const float* wq = Wp + k0 + 16;
            if (W4) { pw0 = *(const float4*)wq; pw1 = *(const float4*)(wq + 4); }
            else {
                pw0 = make_float4(wq[0], wq[1], wq[2], wq[3]);
                pw1 = make_float4(wq[4], wq[5], wq[6], wq[7]);
            }
        }
#pragma unroll
        for (int kk = 0; kk < 16; kk++) {
            float4 a0 = *(const float4*)&As[cur][kk][ty * 4];
            float4 a1 = *(const float4*)&As[cur][kk][64 + ty * 4];
            ulonglong2 bq0 = *(const ulonglong2*)&Bs[cur][kk][tx * 4];
            ulonglong2 bq1 = *(const ulonglong2*)&Bs[cur][kk][64 + tx * 4];
            float ar[8] = {a0.x, a0.y, a0.z, a0.w, a1.x, a1.y, a1.z, a1.w};
#pragma unroll
            for (int i = 0; i < 8; i++) {
                ull aa; dup2(aa, ar[i]);
                ffma2(acc[i][0], aa, bq0.x);
                ffma2(acc[i][1], aa, bq0.y);
                ffma2(acc[i][2], aa, bq1.x);
                ffma2(acc[i][3], aa, bq1.y);
            }
        }
        if (more) {
            int nx = cur ^ 1;
            As[nx][lc + 0][lr] = pa0.x; As[nx][lc + 1][lr] = pa0.y;
            As[nx][lc + 2][lr] = pa0.z; As[nx][lc + 3][lr] = pa0.w;
            As[nx][lc + 4][lr] = pa1.x; As[nx][lc + 5][lr] = pa1.y;
            As[nx][lc + 6][lr] = pa1.z; As[nx][lc + 7][lr] = pa1.w;
            Bs[nx][lc + 0][lr] = pw0.x; Bs[nx][lc + 1][lr] = pw0.y;
            Bs[nx][lc + 2][lr] = pw0.z; Bs[nx][lc + 3][lr] = pw0.w;
            Bs[nx][lc + 4][lr] = pw1.x; Bs[nx][lc + 5][lr] = pw1.y;
            Bs[nx][lc + 6][lr] = pw1.z; Bs[nx][lc + 7][lr] = pw1.w;
        }
        __syncthreads();
        cur ^= 1;
    }

    // ---- small-K tail (x_v @ Wih_x.T, K2 <= 15) ----
    if (K2 > 0) {
        float (*Ta)[128] = (float(*)[128]) & As[0][0][0];
        float (*Tb)[128] = (float(*)[128]) & Bs[0][0][0];
        for (int idx = tid; idx < 128 * K2; idx += 256) {
            int m = idx & 127;
            int k = idx >> 7;
            Ta[k][m] = A2[(size_t)(m0 + m) * lda2 + k];
            int g2 = n0 + m;
            int wr2 = REMAP ? (((g2 & 3) << 8) | (g2 >> 2)) : g2;
            Tb[k][m] = W2[(size_t)wr2 * ldw2 + k];
        }
        __syncthreads();
        for (int kk = 0; kk < K2; kk++) {
            float4 a0 = *(const float4*)&Ta[kk][ty * 4];
            float4 a1 = *(const float4*)&Ta[kk][64 + ty * 4];
            ulonglong2 bq0 = *(const ulonglong2*)&Tb[kk][tx * 4];
            ulonglong2 bq1 = *(const ulonglong2*)&Tb[kk][64 + tx * 4];
            float ar[8] = {a0.x, a0.y, a0.z, a0.w, a1.x, a1.y, a1.z, a1.w};
#pragma unroll
            for (int i = 0; i < 8; i++) {
                ull aa; dup2(aa, ar[i]);
                ffma2(acc[i][0], aa, bq0.x);
                ffma2(acc[i][1], aa, bq0.y);
                ffma2(acc[i][2], aa, bq1.x);
                ffma2(acc[i][3], aa, bq1.y);
            }
        }
    }

    // ---- epilogue ----
    float add[8];
    if (EPI != 2 || addmat == nullptr) {
#pragma unroll
        for (int j = 0; j < 8; j++) {
            int n = n0 + ((j < 4) ? (4 * tx + j) : (64 + 4 * tx + (j - 4)));
            int rn = REMAP ? (((n & 3) << 8) | (n >> 2)) : n;
            float t = 0.f;
            if (b1) t += b1[rn];
            if (b2) t += b2[rn];
            add[j] = t;
        }
    }

    if (EPI == 2) {
        // quadrant q gives hidden unit hu_q = n0/4 + 16q + tx, gates j=0..3
        const int hu0 = (n0 >> 2) + tx;
        const int hu1 = hu0 + 16;
#pragma unroll
        for (int i = 0; i < 8; i++) {
            int m = m0 + ((i < 4) ? (4 * ty + i) : (64 + 4 * ty + (i - 4)));
            float g[8];
#pragma unroll
            for (int j4 = 0; j4 < 4; j4++) {
                float2 f = u2f(acc[i][j4]);
                g[2 * j4] = f.x; g[2 * j4 + 1] = f.y;
            }
            if (addmat) {
                float4 p0 = *(const float4*)(addmat + (size_t)m * Gn + n0 + 4 * tx);
                float4 p1 = *(const float4*)(addmat + (size_t)m * Gn + n0 + 64 + 4 * tx);
                g[0] += p0.x; g[1] += p0.y; g[2] += p0.z; g[3] += p0.w;
                g[4] += p1.x; g[5] += p1.y; g[6] += p1.z; g[7] += p1.w;
            } else {
#pragma unroll
                for (int j = 0; j < 8; j++) g[j] += add[j];
            }
            size_t c0i = (size_t)m * Hn + hu0;
            size_t c1i = (size_t)m * Hn + hu1;
            {
                float iv = fsig(g[0]), fv = fsig(g[1]);
                float gv = tanhf(g[2]), ov = fsig(g[3]);
                float cn = fv * cSt[c0i] + iv * gv;
                cSt[c0i] = cn;
                C[c0i] = ov * tanhf(cn);
            }
            {
                float iv = fsig(g[4]), fv = fsig(g[5]);
                float gv = tanhf(g[6]), ov = fsig(g[7]);
                float cn = fv * cSt[c1i] + iv * gv;
                cSt[c1i] = cn;
                C[c1i] = ov * tanhf(cn);
            }
        }
    } else {
#pragma unroll
        for (int i = 0; i < 8; i++) {
            int m = m0 + ((i < 4) ? (4 * ty + i) : (64 + 4 * ty + (i - 4)));
            float o[8];
#pragma unroll
            for (int j4 = 0; j4 < 4; j4++) {
                float2 f = u2f(acc[i][j4]);
                o[2 * j4]     = f.x + add[2 * j4];
                o[2 * j4 + 1] = f.y + add[2 * j4 + 1];
            }
            if (EPI == 1) {
#pragma unroll
                for (int j = 0; j < 8; j++) o[j] = fmaxf(o[j], 0.f);
            }
            *(float4*)(C + (size_t)m * N + n0 + 4 * tx)      = make_float4(o[0], o[1], o[2], o[3]);
            *(float4*)(C + (size_t)m * N + n0 + 64 + 4 * tx) = make_float4(o[4], o[5], o[6], o[7]);
        }
    }
}

// ---------------- pi head: out[b][v] = tanh(h2[b]·piW + pib) ----------------
__global__ void pi_kernel(const float* __restrict__ h2,
                          const float* __restrict__ piW,
                          const float* __restrict__ pib,
                          float* __restrict__ out, int v) {
    int gw = (blockIdx.x * blockDim.x + threadIdx.x) >> 5;
    int lane = threadIdx.x & 31;
    if (gw >= Bsz) return;
    const float* hr = h2 + (size_t)gw * Hn;
    float s = 0.f;
#pragma unroll
    for (int k = lane; k < Hn; k += 32) s += hr[k] * piW[k];
#pragma unroll
    for (int off = 16; off > 0; off >>= 1)
        s += __shfl_down_sync(0xffffffffu, s, off);
    if (lane == 0)
        out[(size_t)gw * Vn + v] = tanhf(s + pib[0]);
}

// ---------------- launch ----------------------------------------------------
extern "C" void kernel_launch(void* const* d_in, const int* in_sizes, int n_in,
                              void* d_out, int out_size) {
    const float* state  = (const float*)d_in[0];   // [4096, 750]
    const float* l1_Wih = (const float*)d_in[1];   // [1024, 15]
    const float* l1_Whh = (const float*)d_in[2];   // [1024, 256]
    const float* l1_bih = (const float*)d_in[3];
    const float* l1_bhh = (const float*)d_in[4];
    const float* fc1_W  = (const float*)d_in[5];   // [1024, 256]
    const float* fc1_b  = (const float*)d_in[6];
    const float* fc2_W  = (const float*)d_in[7];   // [1024, 1024]
    const float* fc2_b  = (const float*)d_in[8];
    const float* fc3_W  = (const float*)d_in[9];   // [512, 1024]
    const float* fc3_b  = (const float*)d_in[10];
    const float* fc4_W  = (const float*)d_in[11];  // [256, 512]
    const float* fc4_b  = (const float*)d_in[12];
    const float* l2_Wih = (const float*)d_in[13];  // [1024, 271]
    const float* l2_Whh = (const float*)d_in[14];  // [1024, 256]
    const float* l2_bih = (const float*)d_in[15];
    const float* l2_bhh = (const float*)d_in[16];
    const float* pi_W   = (const float*)d_in[17];  // [1, 256]
    const float* pi_b   = (const float*)d_in[18];  // [1]
    float* out = (float*)d_out;                    // [4096, 50]

    float *h1a, *h1b, *c1, *h2a, *h2b, *c2, *m1, *m2, *m3, *m4, *pre2;
    cudaGetSymbolAddress((void**)&h1a, g_h1a);
    cudaGetSymbolAddress((void**)&h1b, g_h1b);
    cudaGetSymbolAddress((void**)&c1,  g_c1);
    cudaGetSymbolAddress((void**)&h2a, g_h2a);
    cudaGetSymbolAddress((void**)&h2b, g_h2b);
    cudaGetSymbolAddress((void**)&c2,  g_c2);
    cudaGetSymbolAddress((void**)&m1, g_m1);
    cudaGetSymbolAddress((void**)&m2, g_m2);
    cudaGetSymbolAddress((void**)&m3, g_m3);
    cudaGetSymbolAddress((void**)&m4, g_m4);
    cudaGetSymbolAddress((void**)&pre2, g_pre2);

    zero_states_kernel<<<(Bsz * Hn + 255) / 256, 256>>>();

    dim3 sgrid(Gn / 128, Bsz / 128);   // 8 x 32

    // ---- LSTM1 scan (fused gate GEMM + cell update), ping-pong h ----
    for (int v = 0; v < Vn; v++) {
        const float* hin  = (v & 1) ? h1b : h1a;
        float*       hout = (v & 1) ? h1a : h1b;
        gemm3<2, 1, 1><<<sgrid, 256>>>(
            hin, Hn, l1_Whh, Hn, Hn,
            state + v * Fn, Vn * Fn, l1_Wih, Fn, Fn,
            l1_bih, l1_bhh, nullptr,
            hout, Gn, c1);
    }
    const float* h1fin = (Vn & 1) ? h1b : h1a;

    // ---- MLP stack (relu) ----
    gemm3<1, 0, 1><<<dim3(1024 / 128, 32), 256>>>(
        h1fin, Hn, fc1_W, Hn, Hn,
        nullptr, 0, nullptr, 0, 0,
        fc1_b, nullptr, nullptr, m1, 1024, nullptr);
    gemm3<1, 0, 1><<<dim3(1024 / 128, 32), 256>>>(
        m1, 1024, fc2_W, 1024, 1024,
        nullptr, 0, nullptr, 0, 0,
        fc2_b, nullptr, nullptr, m2, 1024, nullptr);
    gemm3<1, 0, 1><<<dim3(512 / 128, 32), 256>>>(
        m2, 1024, fc3_W, 1024, 1024,
        nullptr, 0, nullptr, 0, 0,
        fc3_b, nullptr, nullptr, m3, 512, nullptr);
    gemm3<1, 0, 1><<<dim3(256 / 128, 32), 256>>>(
        m3, 512, fc4_W, 512, 512,
        nullptr, 0, nullptr, 0, 0,
        fc4_b, nullptr, nullptr, m4, 256, nullptr);

    // ---- pre2 = m4 @ Wih2[:,15:].T + bih + bhh  (REMAPPED quadrant layout) --
    gemm3<0, 1, 0><<<sgrid, 256>>>(
        m4, 256, l2_Wih + 15, 271, 256,
        nullptr, 0, nullptr, 0, 0,
        l2_bih, l2_bhh, nullptr, pre2, Gn, nullptr);

    // ---- LSTM2 scan (fused) + pi head, ping-pong h ----
    for (int v = 0; v < Vn; v++) {
        const float* hin  = (v & 1) ? h2b : h2a;
        float*       hout = (v & 1) ? h2a : h2b;
        gemm3<2, 1, 1><<<sgrid, 256>>>(
            hin, Hn, l2_Whh, Hn, Hn,
            state + v * Fn, Vn * Fn, l2_Wih, 271, Fn,
            nullptr, nullptr, pre2,
            hout, Gn, c2);
        pi_kernel<<<Bsz / 8, 256>>>(hout, pi_W, pi_b, out, v);
    }
}